// round 2
// baseline (speedup 1.0000x reference)
#include <cuda_runtime.h>

#define CC    512
#define HIDN  128
#define HWN   3136
#define NT    64
#define KT    64
#define LDA   68   // As row stride (floats), 68*4=272B -> 16B aligned rows
#define LDB   68
#define LDH   68
#define EPSV  1e-5f

// Fused: per-batch branch select -> GEMM1 (W1 @ x) -> BN+ReLU (in SMEM) -> GEMM2 (W2 @ h)
// One CTA handles (batch b, 64-pixel tile). 256 threads, 8x4 register tile per thread.
__global__ __launch_bounds__(256, 2)
void msp_fused(const float* __restrict__ x, const int* __restrict__ mod,
               const float* __restrict__ w1_rgb, const float* __restrict__ rm_rgb,
               const float* __restrict__ rv_rgb, const float* __restrict__ g_rgb,
               const float* __restrict__ b_rgb,  const float* __restrict__ w2_rgb,
               const float* __restrict__ w1_inf, const float* __restrict__ rm_inf,
               const float* __restrict__ rv_inf, const float* __restrict__ g_inf,
               const float* __restrict__ b_inf,  const float* __restrict__ w2_inf,
               float* __restrict__ out)
{
    extern __shared__ float smem[];
    float* As     = smem;                    // [128][LDA]  W1 k-chunk, reused for W2 chunks
    float* Bs     = As + HIDN * LDA;         // [KT][LDB]   x chunk
    float* hs     = Bs + KT * LDB;           // [HIDN][LDH] hidden activations (post BN+ReLU)
    float* sscale = hs + HIDN * LDH;         // [128]
    float* sshift = sscale + HIDN;           // [128]

    const int b   = blockIdx.y;
    const int p0  = blockIdx.x * NT;
    const int tid = threadIdx.x;
    const int mi  = tid >> 4, ni = tid & 15;
    const int m0  = mi * 8,   n0 = ni * 4;

    const bool rgb = (mod[b] == 1);
    const float* w1 = rgb ? w1_rgb : w1_inf;
    const float* w2 = rgb ? w2_rgb : w2_inf;
    const float* rm = rgb ? rm_rgb : rm_inf;
    const float* rv = rgb ? rv_rgb : rv_inf;
    const float* gg = rgb ? g_rgb  : g_inf;
    const float* bb = rgb ? b_rgb  : b_inf;

    // BN folded scale/shift (ordered before first use by the first __syncthreads below)
    if (tid < HIDN) {
        float s = gg[tid] * rsqrtf(rv[tid] + EPSV);
        sscale[tid] = s;
        sshift[tid] = bb[tid] - rm[tid] * s;
    }

    const float* xb = x + ((size_t)b * CC) * HWN + p0;

    float acc[8][4];
    #pragma unroll
    for (int i = 0; i < 8; i++)
        #pragma unroll
        for (int j = 0; j < 4; j++) acc[i][j] = 0.f;

    // ---------------- GEMM1: h[128,64] = W1[128,512] @ x[512,64] ----------------
    for (int k0 = 0; k0 < CC; k0 += KT) {
        // stage W1 chunk: As[m][k] = w1[m][k0+k]   (128 rows x 16 float4)
        #pragma unroll
        for (int t = 0; t < 8; t++) {
            int idx = tid + t * 256;            // 0..2047
            int r = idx >> 4, c4 = (idx & 15) << 2;
            float4 v = *(const float4*)&w1[r * CC + k0 + c4];
            *(float4*)&As[r * LDA + c4] = v;
        }
        // stage x chunk: Bs[k][n] = x[b][k0+k][p0+n]   (64 rows x 16 float4)
        #pragma unroll
        for (int t = 0; t < 4; t++) {
            int idx = tid + t * 256;            // 0..1023
            int r = idx >> 4, c4 = (idx & 15) << 2;
            float4 v = *(const float4*)&xb[(size_t)(k0 + r) * HWN + c4];
            *(float4*)&Bs[r * LDB + c4] = v;
        }
        __syncthreads();

        #pragma unroll 4
        for (int k = 0; k < KT; k++) {
            float4 bv = *(const float4*)&Bs[k * LDB + n0];
            float a[8];
            #pragma unroll
            for (int i = 0; i < 8; i++) a[i] = As[(m0 + i) * LDA + k];
            #pragma unroll
            for (int i = 0; i < 8; i++) {
                acc[i][0] = fmaf(a[i], bv.x, acc[i][0]);
                acc[i][1] = fmaf(a[i], bv.y, acc[i][1]);
                acc[i][2] = fmaf(a[i], bv.z, acc[i][2]);
                acc[i][3] = fmaf(a[i], bv.w, acc[i][3]);
            }
        }
        __syncthreads();
    }

    // BN + ReLU epilogue -> hs (stays in SMEM, never touches HBM)
    #pragma unroll
    for (int i = 0; i < 8; i++) {
        int m = m0 + i;
        float s = sscale[m], sh = sshift[m];
        float4 v;
        v.x = fmaxf(fmaf(acc[i][0], s, sh), 0.f);
        v.y = fmaxf(fmaf(acc[i][1], s, sh), 0.f);
        v.z = fmaxf(fmaf(acc[i][2], s, sh), 0.f);
        v.w = fmaxf(fmaf(acc[i][3], s, sh), 0.f);
        *(float4*)&hs[m * LDH + n0] = v;
    }
    __syncthreads();

    // ---------------- GEMM2: out[512,64] = W2[512,128] @ hs[128,64] ----------------
    float* outb = out + ((size_t)b * CC) * HWN + p0;
    for (int chunk = 0; chunk < 4; chunk++) {
        #pragma unroll
        for (int i = 0; i < 8; i++)
            #pragma unroll
            for (int j = 0; j < 4; j++) acc[i][j] = 0.f;

        for (int kc = 0; kc < HIDN; kc += KT) {
            // stage W2 chunk into As: As[r][c] = w2[chunk*128+r][kc+c]
            #pragma unroll
            for (int t = 0; t < 8; t++) {
                int idx = tid + t * 256;
                int r = idx >> 4, c4 = (idx & 15) << 2;
                float4 v = *(const float4*)&w2[(chunk * HIDN + r) * HIDN + kc + c4];
                *(float4*)&As[r * LDA + c4] = v;
            }
            __syncthreads();

            #pragma unroll 4
            for (int k = 0; k < KT; k++) {
                float4 bv = *(const float4*)&hs[(kc + k) * LDH + n0];
                float a[8];
                #pragma unroll
                for (int i = 0; i < 8; i++) a[i] = As[(m0 + i) * LDA + k];
                #pragma unroll
                for (int i = 0; i < 8; i++) {
                    acc[i][0] = fmaf(a[i], bv.x, acc[i][0]);
                    acc[i][1] = fmaf(a[i], bv.y, acc[i][1]);
                    acc[i][2] = fmaf(a[i], bv.z, acc[i][2]);
                    acc[i][3] = fmaf(a[i], bv.w, acc[i][3]);
                }
            }
            __syncthreads();
        }

        #pragma unroll
        for (int i = 0; i < 8; i++) {
            float4 v = make_float4(acc[i][0], acc[i][1], acc[i][2], acc[i][3]);
            *(float4*)&outb[(size_t)(chunk * HIDN + m0 + i) * HWN + n0] = v;
        }
    }
}

extern "C" void kernel_launch(void* const* d_in, const int* in_sizes, int n_in,
                              void* d_out, int out_size)
{
    const float* x      = (const float*)d_in[0];
    const int*   mod    = (const int*)  d_in[1];
    const float* w1_rgb = (const float*)d_in[2];
    const float* rm_rgb = (const float*)d_in[3];
    const float* rv_rgb = (const float*)d_in[4];
    const float* g_rgb  = (const float*)d_in[5];
    const float* b_rgb  = (const float*)d_in[6];
    const float* w2_rgb = (const float*)d_in[7];
    const float* w1_inf = (const float*)d_in[8];
    const float* rm_inf = (const float*)d_in[9];
    const float* rv_inf = (const float*)d_in[10];
    const float* g_inf  = (const float*)d_in[11];
    const float* b_inf  = (const float*)d_in[12];
    const float* w2_inf = (const float*)d_in[13];
    float* out = (float*)d_out;

    const int B = in_sizes[1];  // mod has one entry per batch element

    const size_t smem_bytes = (size_t)(HIDN * LDA + KT * LDB + HIDN * LDH + 2 * HIDN) * sizeof(float);
    cudaFuncSetAttribute(msp_fused, cudaFuncAttributeMaxDynamicSharedMemorySize, (int)smem_bytes);

    dim3 grid(HWN / NT, B);
    msp_fused<<<grid, 256, smem_bytes>>>(
        x, mod,
        w1_rgb, rm_rgb, rv_rgb, g_rgb, b_rgb, w2_rgb,
        w1_inf, rm_inf, rv_inf, g_inf, b_inf, w2_inf,
        out);
}

// round 5
// speedup vs baseline: 2.5174x; 2.5174x over previous
#include <cuda_runtime.h>
#include <cuda_bf16.h>
#include <cstdint>

#define CC    512
#define HIDN  128
#define HWN   3136
#define NT    64
#define EPSV  1e-5f

// ---------------- precomputed weights (bf16 hi/lo) + folded BN ----------------
__device__ __nv_bfloat16 g_w1hi[2][HIDN * CC];
__device__ __nv_bfloat16 g_w1lo[2][HIDN * CC];
__device__ __nv_bfloat16 g_w2hi[2][CC * HIDN];
__device__ __nv_bfloat16 g_w2lo[2][CC * HIDN];
__device__ float g_scale[2][HIDN];
__device__ float g_shift[2][HIDN];

__global__ void prep_kernel(const float* __restrict__ w1_rgb, const float* __restrict__ w2_rgb,
                            const float* __restrict__ w1_inf, const float* __restrict__ w2_inf,
                            const float* __restrict__ rm_rgb, const float* __restrict__ rv_rgb,
                            const float* __restrict__ g_rgb,  const float* __restrict__ b_rgb,
                            const float* __restrict__ rm_inf, const float* __restrict__ rv_inf,
                            const float* __restrict__ g_inf,  const float* __restrict__ b_inf)
{
    int idx = blockIdx.x * blockDim.x + threadIdx.x;   // 0 .. 4*65536-1
    int seg = idx >> 16;
    int off = idx & 65535;
    const float* src;
    __nv_bfloat16 *dh, *dl;
    switch (seg) {
        case 0:  src = w1_rgb; dh = g_w1hi[1]; dl = g_w1lo[1]; break;
        case 1:  src = w1_inf; dh = g_w1hi[0]; dl = g_w1lo[0]; break;
        case 2:  src = w2_rgb; dh = g_w2hi[1]; dl = g_w2lo[1]; break;
        default: src = w2_inf; dh = g_w2hi[0]; dl = g_w2lo[0]; break;
    }
    float f = src[off];
    __nv_bfloat16 h = __float2bfloat16(f);
    dh[off] = h;
    dl[off] = __float2bfloat16(f - __bfloat162float(h));

    if (blockIdx.x == 0 && threadIdx.x < 256) {
        int i = threadIdx.x & 127;
        if (threadIdx.x < 128) {
            float s = g_rgb[i] * rsqrtf(rv_rgb[i] + EPSV);
            g_scale[1][i] = s;
            g_shift[1][i] = b_rgb[i] - rm_rgb[i] * s;
        } else {
            float s = g_inf[i] * rsqrtf(rv_inf[i] + EPSV);
            g_scale[0][i] = s;
            g_shift[0][i] = b_inf[i] - rm_inf[i] * s;
        }
    }
}

// ---------------- helpers ----------------
__device__ __forceinline__ uint32_t smem_u32(const void* p) {
    uint32_t a;
    asm("{ .reg .u64 t; cvta.to.shared.u64 t, %1; cvt.u32.u64 %0, t; }" : "=r"(a) : "l"(p));
    return a;
}
#define SW128(o) ((o) ^ ((((uint32_t)(o)) >> 3) & 0x70u))

__device__ __forceinline__ void ldsm4(uint32_t* r, uint32_t addr) {
    asm volatile("ldmatrix.sync.aligned.m8n8.x4.shared.b16 {%0,%1,%2,%3}, [%4];"
                 : "=r"(r[0]), "=r"(r[1]), "=r"(r[2]), "=r"(r[3]) : "r"(addr));
}
__device__ __forceinline__ void ldsm4t(uint32_t* r, uint32_t addr) {
    asm volatile("ldmatrix.sync.aligned.m8n8.x4.trans.shared.b16 {%0,%1,%2,%3}, [%4];"
                 : "=r"(r[0]), "=r"(r[1]), "=r"(r[2]), "=r"(r[3]) : "r"(addr));
}
__device__ __forceinline__ void mma_bf16(float* d, const uint32_t* a, const uint32_t* b) {
    asm volatile("mma.sync.aligned.m16n8k16.row.col.f32.bf16.bf16.f32 "
                 "{%0,%1,%2,%3}, {%4,%5,%6,%7}, {%8,%9}, {%0,%1,%2,%3};"
                 : "+f"(d[0]), "+f"(d[1]), "+f"(d[2]), "+f"(d[3])
                 : "r"(a[0]), "r"(a[1]), "r"(a[2]), "r"(a[3]), "r"(b[0]), "r"(b[1]));
}

// ---------------- smem layout (bytes, dynamic) ----------------
// [0, 64K)    staging: GEMM1: Ahi 16K | Alo 16K | Bhi 8K | Blo 8K
//                      GEMM2: W2hi 32K (two 64k halves) | W2lo 32K
// [64K, 80K)  hs hi   [128 k][64 n] bf16, 128B rows, SW128
// [80K, 96K)  hs lo
// [96K, ..)   sscale 512B | sshift 512B
#define OFF_HS_HI 65536
#define OFF_HS_LO 81920
#define OFF_SCALE 98304
#define OFF_SHIFT 98816
#define SM_TOTAL  99328

__global__ __launch_bounds__(256, 2)
void msp_mma(const float* __restrict__ x, const int* __restrict__ mod, float* __restrict__ out)
{
    extern __shared__ char smem[];
    const uint32_t sb = smem_u32(smem);
    const int tid  = threadIdx.x;
    const int wid  = tid >> 5;
    const int lane = tid & 31;
    const int b    = blockIdx.y;
    const int p0   = blockIdx.x * NT;
    const int br   = (mod[b] == 1) ? 1 : 0;

    float* sscale = (float*)(smem + OFF_SCALE);
    float* sshift = (float*)(smem + OFF_SHIFT);
    if (tid < HIDN) {
        sscale[tid] = g_scale[br][tid];
        sshift[tid] = g_shift[br][tid];
    }

    const __nv_bfloat16* w1h = g_w1hi[br];
    const __nv_bfloat16* w1l = g_w1lo[br];
    const __nv_bfloat16* w2h = g_w2hi[br];
    const __nv_bfloat16* w2l = g_w2lo[br];
    const float* xb = x + ((size_t)b * CC) * HWN + p0;

    // warp tile: 4 warps along M, 2 along N; warp tile 32x32
    const int wm = (wid >> 1) * 32;
    const int wn = (wid & 1) * 32;
    // ldmatrix per-thread address components
    const int lt = lane >> 3, lr = lane & 7;
    const int m_off  = (lt & 1) * 8 + lr;   // A: row within m16, B: row within k16
    const int ko_off = (lt >> 1) * 8;       // A: k byte-block, B: n byte-block

    float acc[2][4][4];
    #pragma unroll
    for (int mt = 0; mt < 2; mt++)
        #pragma unroll
        for (int nt = 0; nt < 4; nt++)
            #pragma unroll
            for (int j = 0; j < 4; j++) acc[mt][nt][j] = 0.f;

    // =============== GEMM1: h[128,64] = W1[128,512] @ x[512,64] ===============
    for (int c = 0; c < 8; c++) {
        const int k0 = c * 64;
        // stage W1 chunk hi/lo: [128 m][64 k], 128B rows, SW128
        #pragma unroll
        for (int i = 0; i < 4; i++) {
            int idx = tid + i * 256;             // 0..1023
            int r = idx >> 3, c8 = (idx & 7) * 8;
            uint32_t off = SW128(r * 128 + c8 * 2);
            *(uint4*)(smem + off)         = *(const uint4*)(w1h + r * CC + k0 + c8);
            *(uint4*)(smem + 16384 + off) = *(const uint4*)(w1l + r * CC + k0 + c8);
        }
        // stage x chunk hi/lo: [64 k][64 n], 128B rows, SW128 (on-the-fly fp32->bf16 split)
        #pragma unroll
        for (int i = 0; i < 4; i++) {
            int idx = tid + i * 256;             // 0..1023
            int r = idx >> 4, c4 = (idx & 15) * 4;
            float4 v = *(const float4*)(xb + (size_t)(k0 + r) * HWN + c4);
            __nv_bfloat162 h01 = __floats2bfloat162_rn(v.x, v.y);
            __nv_bfloat162 h23 = __floats2bfloat162_rn(v.z, v.w);
            __nv_bfloat162 l01 = __floats2bfloat162_rn(v.x - __bfloat162float(h01.x),
                                                       v.y - __bfloat162float(h01.y));
            __nv_bfloat162 l23 = __floats2bfloat162_rn(v.z - __bfloat162float(h23.x),
                                                       v.w - __bfloat162float(h23.y));
            uint32_t off = SW128(r * 128 + c4 * 2);
            *(uint2*)(smem + 32768 + off) = make_uint2(*(uint32_t*)&h01, *(uint32_t*)&h23);
            *(uint2*)(smem + 40960 + off) = make_uint2(*(uint32_t*)&l01, *(uint32_t*)&l23);
        }
        __syncthreads();

        #pragma unroll
        for (int ks = 0; ks < 4; ks++) {
            const int kb = ks * 16;
            uint32_t ah[2][4], al[2][4], bh[2][4], bl[2][4];
            #pragma unroll
            for (int mt = 0; mt < 2; mt++) {
                uint32_t o = SW128((uint32_t)(wm + mt * 16 + m_off) * 128 + (kb + ko_off) * 2);
                ldsm4(ah[mt], sb + o);
                ldsm4(al[mt], sb + 16384 + o);
            }
            #pragma unroll
            for (int bt = 0; bt < 2; bt++) {
                uint32_t o = SW128((uint32_t)(kb + m_off) * 128 + (wn + bt * 16 + ko_off) * 2);
                ldsm4t(bh[bt], sb + 32768 + o);
                ldsm4t(bl[bt], sb + 40960 + o);
            }
            #pragma unroll
            for (int mt = 0; mt < 2; mt++)
                #pragma unroll
                for (int nt = 0; nt < 4; nt++) {
                    const uint32_t* ph = &bh[nt >> 1][(nt & 1) * 2];
                    const uint32_t* pl = &bl[nt >> 1][(nt & 1) * 2];
                    mma_bf16(acc[mt][nt], ah[mt], ph);
                    mma_bf16(acc[mt][nt], ah[mt], pl);
                    mma_bf16(acc[mt][nt], al[mt], ph);
                }
        }
        __syncthreads();
    }

    // ---- GEMM1 epilogue: BN+ReLU, split hi/lo, write hs [k=hid][n] ----
    {
        const int qr = lane >> 2, qc = (lane & 3) * 2;
        #pragma unroll
        for (int mt = 0; mt < 2; mt++)
            #pragma unroll
            for (int nt = 0; nt < 4; nt++) {
                int r0 = wm + mt * 16 + qr;
                int nc = wn + nt * 8 + qc;
                float s0 = sscale[r0],     f0 = sshift[r0];
                float s1 = sscale[r0 + 8], f1 = sshift[r0 + 8];
                float v00 = fmaxf(fmaf(acc[mt][nt][0], s0, f0), 0.f);
                float v01 = fmaxf(fmaf(acc[mt][nt][1], s0, f0), 0.f);
                float v10 = fmaxf(fmaf(acc[mt][nt][2], s1, f1), 0.f);
                float v11 = fmaxf(fmaf(acc[mt][nt][3], s1, f1), 0.f);
                __nv_bfloat162 hp0 = __floats2bfloat162_rn(v00, v01);
                __nv_bfloat162 lp0 = __floats2bfloat162_rn(v00 - __bfloat162float(hp0.x),
                                                           v01 - __bfloat162float(hp0.y));
                __nv_bfloat162 hp1 = __floats2bfloat162_rn(v10, v11);
                __nv_bfloat162 lp1 = __floats2bfloat162_rn(v10 - __bfloat162float(hp1.x),
                                                           v11 - __bfloat162float(hp1.y));
                uint32_t o0 = SW128((uint32_t)r0 * 128 + nc * 2);
                uint32_t o1 = SW128((uint32_t)(r0 + 8) * 128 + nc * 2);
                *(uint32_t*)(smem + OFF_HS_HI + o0) = *(uint32_t*)&hp0;
                *(uint32_t*)(smem + OFF_HS_LO + o0) = *(uint32_t*)&lp0;
                *(uint32_t*)(smem + OFF_HS_HI + o1) = *(uint32_t*)&hp1;
                *(uint32_t*)(smem + OFF_HS_LO + o1) = *(uint32_t*)&lp1;
            }
    }
    __syncthreads();

    // =============== GEMM2: out[512,64] = W2[512,128] @ h[128,64] ===============
    for (int mc = 0; mc < 4; mc++) {
        // stage W2 chunk hi/lo: [128 m][128 k] as two 64-k halves, SW128
        #pragma unroll
        for (int i = 0; i < 8; i++) {
            int idx = tid + i * 256;             // 0..2047
            int r = idx >> 4, c8 = (idx & 15) * 8;
            uint32_t off = ((c8 >= 64) ? 16384u : 0u) + SW128(r * 128 + (c8 & 63) * 2);
            *(uint4*)(smem + off)         = *(const uint4*)(w2h + (mc * HIDN + r) * HIDN + c8);
            *(uint4*)(smem + 32768 + off) = *(const uint4*)(w2l + (mc * HIDN + r) * HIDN + c8);
        }
        __syncthreads();

        float acc2[2][4][4];
        #pragma unroll
        for (int mt = 0; mt < 2; mt++)
            #pragma unroll
            for (int nt = 0; nt < 4; nt++)
                #pragma unroll
                for (int j = 0; j < 4; j++) acc2[mt][nt][j] = 0.f;

        #pragma unroll
        for (int ks = 0; ks < 8; ks++) {
            const uint32_t half = (ks >> 2) * 16384u;
            const int kk = (ks & 3) * 16;
            uint32_t ah[2][4], al[2][4], bh[2][4], bl[2][4];
            #pragma unroll
            for (int mt = 0; mt < 2; mt++) {
                uint32_t o = SW128((uint32_t)(wm + mt * 16 + m_off) * 128 + (kk + ko_off) * 2);
                ldsm4(ah[mt], sb + half + o);
                ldsm4(al[mt], sb + 32768 + half + o);
            }
            #pragma unroll
            for (int bt = 0; bt < 2; bt++) {
                uint32_t o = SW128((uint32_t)(ks * 16 + m_off) * 128 + (wn + bt * 16 + ko_off) * 2);
                ldsm4t(bh[bt], sb + OFF_HS_HI + o);
                ldsm4t(bl[bt], sb + OFF_HS_LO + o);
            }
            #pragma unroll
            for (int mt = 0; mt < 2; mt++)
                #pragma unroll
                for (int nt = 0; nt < 4; nt++) {
                    const uint32_t* ph = &bh[nt >> 1][(nt & 1) * 2];
                    const uint32_t* pl = &bl[nt >> 1][(nt & 1) * 2];
                    mma_bf16(acc2[mt][nt], ah[mt], ph);
                    mma_bf16(acc2[mt][nt], ah[mt], pl);
                    mma_bf16(acc2[mt][nt], al[mt], ph);
                }
        }

        // writeout fp32
        {
            const int qr = lane >> 2, qc = (lane & 3) * 2;
            #pragma unroll
            for (int mt = 0; mt < 2; mt++)
                #pragma unroll
                for (int nt = 0; nt < 4; nt++) {
                    int m = mc * HIDN + wm + mt * 16 + qr;
                    float* orow = out + ((size_t)b * CC + m) * HWN + p0 + wn + nt * 8 + qc;
                    *(float2*)orow                     = make_float2(acc2[mt][nt][0], acc2[mt][nt][1]);
                    *(float2*)(orow + (size_t)8 * HWN) = make_float2(acc2[mt][nt][2], acc2[mt][nt][3]);
                }
        }
        __syncthreads();
    }
}

extern "C" void kernel_launch(void* const* d_in, const int* in_sizes, int n_in,
                              void* d_out, int out_size)
{
    const float* x      = (const float*)d_in[0];
    const int*   mod    = (const int*)  d_in[1];
    const float* w1_rgb = (const float*)d_in[2];
    const float* rm_rgb = (const float*)d_in[3];
    const float* rv_rgb = (const float*)d_in[4];
    const float* g_rgb  = (const float*)d_in[5];
    const float* b_rgb  = (const float*)d_in[6];
    const float* w2_rgb = (const float*)d_in[7];
    const float* w1_inf = (const float*)d_in[8];
    const float* rm_inf = (const float*)d_in[9];
    const float* rv_inf = (const float*)d_in[10];
    const float* g_inf  = (const float*)d_in[11];
    const float* b_inf  = (const float*)d_in[12];
    const float* w2_inf = (const float*)d_in[13];
    float* out = (float*)d_out;

    const int B = in_sizes[1];

    prep_kernel<<<1024, 256>>>(w1_rgb, w2_rgb, w1_inf, w2_inf,
                               rm_rgb, rv_rgb, g_rgb, b_rgb,
                               rm_inf, rv_inf, g_inf, b_inf);

    cudaFuncSetAttribute(msp_mma, cudaFuncAttributeMaxDynamicSharedMemorySize, SM_TOTAL);
    dim3 grid(HWN / NT, B);
    msp_mma<<<grid, 256, SM_TOTAL>>>(x, mod, out);
}

// round 14
// speedup vs baseline: 2.6465x; 1.0513x over previous
#include <cuda_runtime.h>
#include <cuda_bf16.h>
#include <cstdint>

#define CC    512
#define HIDN  128
#define HWN   3136
#define NT    64
#define EPSV  1e-5f

// ---------------- precomputed weights (bf16 hi/lo) + folded BN ----------------
__device__ __nv_bfloat16 g_w1hi[2][HIDN * CC];
__device__ __nv_bfloat16 g_w1lo[2][HIDN * CC];
__device__ __nv_bfloat16 g_w2hi[2][CC * HIDN];
__device__ __nv_bfloat16 g_w2lo[2][CC * HIDN];
__device__ float g_scale[2][HIDN];
__device__ float g_shift[2][HIDN];

__global__ void prep_kernel(const float* __restrict__ w1_rgb, const float* __restrict__ w2_rgb,
                            const float* __restrict__ w1_inf, const float* __restrict__ w2_inf,
                            const float* __restrict__ rm_rgb, const float* __restrict__ rv_rgb,
                            const float* __restrict__ g_rgb,  const float* __restrict__ b_rgb,
                            const float* __restrict__ rm_inf, const float* __restrict__ rv_inf,
                            const float* __restrict__ g_inf,  const float* __restrict__ b_inf)
{
    int idx = blockIdx.x * blockDim.x + threadIdx.x;
    int seg = idx >> 16;
    int off = idx & 65535;
    const float* src;
    __nv_bfloat16 *dh, *dl;
    switch (seg) {
        case 0:  src = w1_rgb; dh = g_w1hi[1]; dl = g_w1lo[1]; break;
        case 1:  src = w1_inf; dh = g_w1hi[0]; dl = g_w1lo[0]; break;
        case 2:  src = w2_rgb; dh = g_w2hi[1]; dl = g_w2lo[1]; break;
        default: src = w2_inf; dh = g_w2hi[0]; dl = g_w2lo[0]; break;
    }
    float f = src[off];
    __nv_bfloat16 h = __float2bfloat16(f);
    dh[off] = h;
    dl[off] = __float2bfloat16(f - __bfloat162float(h));

    if (blockIdx.x == 0 && threadIdx.x < 256) {
        int i = threadIdx.x & 127;
        if (threadIdx.x < 128) {
            float s = g_rgb[i] * rsqrtf(rv_rgb[i] + EPSV);
            g_scale[1][i] = s;
            g_shift[1][i] = b_rgb[i] - rm_rgb[i] * s;
        } else {
            float s = g_inf[i] * rsqrtf(rv_inf[i] + EPSV);
            g_scale[0][i] = s;
            g_shift[0][i] = b_inf[i] - rm_inf[i] * s;
        }
    }
}

// ---------------- helpers ----------------
__device__ __forceinline__ uint32_t smem_u32(const void* p) {
    uint32_t a;
    asm("{ .reg .u64 t; cvta.to.shared.u64 t, %1; cvt.u32.u64 %0, t; }" : "=r"(a) : "l"(p));
    return a;
}
#define SW128(o) ((o) ^ ((((uint32_t)(o)) >> 3) & 0x70u))

__device__ __forceinline__ void ldsm4(uint32_t* r, uint32_t addr) {
    asm volatile("ldmatrix.sync.aligned.m8n8.x4.shared.b16 {%0,%1,%2,%3}, [%4];"
                 : "=r"(r[0]), "=r"(r[1]), "=r"(r[2]), "=r"(r[3]) : "r"(addr));
}
__device__ __forceinline__ void ldsm4t(uint32_t* r, uint32_t addr) {
    asm volatile("ldmatrix.sync.aligned.m8n8.x4.trans.shared.b16 {%0,%1,%2,%3}, [%4];"
                 : "=r"(r[0]), "=r"(r[1]), "=r"(r[2]), "=r"(r[3]) : "r"(addr));
}
__device__ __forceinline__ void mma_bf16(float* d, const uint32_t* a, const uint32_t* b) {
    asm volatile("mma.sync.aligned.m16n8k16.row.col.f32.bf16.bf16.f32 "
                 "{%0,%1,%2,%3}, {%4,%5,%6,%7}, {%8,%9}, {%0,%1,%2,%3};"
                 : "+f"(d[0]), "+f"(d[1]), "+f"(d[2]), "+f"(d[3])
                 : "r"(a[0]), "r"(a[1]), "r"(a[2]), "r"(a[3]), "r"(b[0]), "r"(b[1]));
}
__device__ __forceinline__ void cp16(uint32_t dst, const void* src) {
    asm volatile("cp.async.cg.shared.global [%0], [%1], 16;" :: "r"(dst), "l"(src));
}
#define CP_COMMIT() asm volatile("cp.async.commit_group;" ::: "memory")
#define CP_WAIT0()  asm volatile("cp.async.wait_group 0;" ::: "memory")

// ---------------- smem layout (bytes, dynamic) ----------------
// [0,32K)      A stages: 2 x 16K  (each: hi 8K [64 rows x 128B, two m-halves], lo 8K)
// [32K,48K)    xs stages: 2 x 8K  (raw fp32 x chunk [32k x 64n])
// [48K,64K)    B bf16 stages: 2 x 8K (each: hi 4K [32 rows x 128B], lo 4K)
// [64K,96K)    hs: hi 16K, lo 16K   [128 k x 64 n], 128B rows, SW128
// [96K,97K)    sscale 512B | sshift 512B
#define OFF_A     0
#define OFF_XS    32768
#define OFF_B     49152
#define OFF_HS_HI 65536
#define OFF_HS_LO 81920
#define OFF_SCALE 98304
#define OFF_SHIFT 98816
#define SM_TOTAL  99328

struct Frags { uint32_t ah[2][4], al[2][4], bh[2][4], bl[2][4]; };

__device__ __forceinline__ void compute_chunk(
    const uint32_t sb, uint32_t abase, uint32_t bhibase, uint32_t blobase, int brow0,
    int wm, int wn, int m_off, int ko_off, float acc[2][4][4])
{
    #pragma unroll
    for (int ks = 0; ks < 32; ks += 16) {
        Frags f;
        #pragma unroll
        for (int mt = 0; mt < 2; mt++) {
            int m = wm + mt * 16 + m_off;
            uint32_t o = SW128((uint32_t)(m & 63) * 128 + (m & 64) + (ks + ko_off) * 2);
            ldsm4(f.ah[mt], sb + abase + o);
            ldsm4(f.al[mt], sb + abase + 8192 + o);
        }
        #pragma unroll
        for (int bt = 0; bt < 2; bt++) {
            uint32_t o = SW128((uint32_t)(brow0 + ks + m_off) * 128 + (wn + bt * 16 + ko_off) * 2);
            ldsm4t(f.bh[bt], sb + bhibase + o);
            ldsm4t(f.bl[bt], sb + blobase + o);
        }
        #pragma unroll
        for (int mt = 0; mt < 2; mt++)
            #pragma unroll
            for (int nt = 0; nt < 4; nt++) {
                const uint32_t* ph = &f.bh[nt >> 1][(nt & 1) * 2];
                const uint32_t* pl = &f.bl[nt >> 1][(nt & 1) * 2];
                mma_bf16(acc[mt][nt], f.ah[mt], ph);
                mma_bf16(acc[mt][nt], f.ah[mt], pl);
                mma_bf16(acc[mt][nt], f.al[mt], ph);
            }
    }
}

__global__ __launch_bounds__(256, 2)
void msp_pipe(const float* __restrict__ x, const int* __restrict__ mod, float* __restrict__ out)
{
    extern __shared__ char smem[];
    const uint32_t sb = smem_u32(smem);
    const int tid  = threadIdx.x;
    const int wid  = tid >> 5;
    const int lane = tid & 31;
    const int b    = blockIdx.y;
    const int p0   = blockIdx.x * NT;
    const int br   = (mod[b] == 1) ? 1 : 0;

    float* sscale = (float*)(smem + OFF_SCALE);
    float* sshift = (float*)(smem + OFF_SHIFT);
    if (tid < HIDN) {
        sscale[tid] = g_scale[br][tid];
        sshift[tid] = g_shift[br][tid];
    }

    const __nv_bfloat16* w1h = g_w1hi[br];
    const __nv_bfloat16* w1l = g_w1lo[br];
    const __nv_bfloat16* w2h = g_w2hi[br];
    const __nv_bfloat16* w2l = g_w2lo[br];
    const float* xb = x + ((size_t)b * CC) * HWN + p0;

    const int wm = (wid >> 1) * 32;
    const int wn = (wid & 1) * 32;
    const int lt = lane >> 3, lr = lane & 7;
    const int m_off  = (lt & 1) * 8 + lr;
    const int ko_off = (lt >> 1) * 8;

    // ---- chunk issue: chunks 0..15 = GEMM1 (W1 k-chunk + x chunk), 16..31 = GEMM2 (W2 chunk) ----
    auto issue_chunk = [&](int c) {
        const uint32_t abase = OFF_A + (uint32_t)(c & 1) * 16384;
        if (c < 16) {
            const int k0 = c * 32;
            #pragma unroll
            for (int i = 0; i < 4; i++) {
                int u = tid + i * 256;              // 0..1023 ; <512 = hi, >=512 = lo
                int m = (u & 511) >> 2, q = u & 3;
                const __nv_bfloat16* w = (u < 512) ? w1h : w1l;
                uint32_t dst = abase + ((u < 512) ? 0u : 8192u)
                             + SW128((uint32_t)(m & 63) * 128 + (m & 64) + q * 16);
                cp16(sb + dst, w + m * CC + k0 + q * 8);
            }
            const uint32_t xbase = OFF_XS + (uint32_t)(c & 1) * 8192;
            #pragma unroll
            for (int i = 0; i < 2; i++) {
                int u = tid + i * 256;              // 0..511
                int r = u >> 4, q = u & 15;
                cp16(sb + xbase + r * 256 + q * 16, xb + (size_t)(k0 + r) * HWN + q * 4);
            }
        } else {
            const int j = c - 16, mc = j >> 2, kc = j & 3;
            #pragma unroll
            for (int i = 0; i < 4; i++) {
                int u = tid + i * 256;
                int m = (u & 511) >> 2, q = u & 3;
                const __nv_bfloat16* w = (u < 512) ? w2h : w2l;
                uint32_t dst = abase + ((u < 512) ? 0u : 8192u)
                             + SW128((uint32_t)(m & 63) * 128 + (m & 64) + q * 16);
                cp16(sb + dst, w + (mc * 128 + m) * HIDN + kc * 32 + q * 8);
            }
        }
        CP_COMMIT();
    };

    issue_chunk(0);

    float acc[2][4][4];
    #pragma unroll
    for (int mt = 0; mt < 2; mt++)
        #pragma unroll
        for (int nt = 0; nt < 4; nt++)
            #pragma unroll
            for (int j = 0; j < 4; j++) acc[mt][nt][j] = 0.f;

    const int qr = lane >> 2, qc = (lane & 3) * 2;

    for (int c = 0; c < 32; c++) {
        CP_WAIT0();

        if (c < 16) {
            // convert x chunk c: fp32 staging -> bf16 hi/lo B buffers (SW128)
            const char* xs = smem + OFF_XS + (uint32_t)(c & 1) * 8192;
            char* bdst = smem + OFF_B + (uint32_t)(c & 1) * 8192;
            #pragma unroll
            for (int i = 0; i < 2; i++) {
                int u = tid + i * 256;             // 0..511
                int r = u >> 4, c4 = (u & 15) * 4;
                float4 v = *(const float4*)(xs + r * 256 + c4 * 4);
                __nv_bfloat162 h01 = __floats2bfloat162_rn(v.x, v.y);
                __nv_bfloat162 h23 = __floats2bfloat162_rn(v.z, v.w);
                __nv_bfloat162 l01 = __floats2bfloat162_rn(v.x - __bfloat162float(h01.x),
                                                           v.y - __bfloat162float(h01.y));
                __nv_bfloat162 l23 = __floats2bfloat162_rn(v.z - __bfloat162float(h23.x),
                                                           v.w - __bfloat162float(h23.y));
                uint32_t off = SW128((uint32_t)r * 128 + c4 * 2);
                *(uint2*)(bdst + off)        = make_uint2(*(uint32_t*)&h01, *(uint32_t*)&h23);
                *(uint2*)(bdst + 4096 + off) = make_uint2(*(uint32_t*)&l01, *(uint32_t*)&l23);
            }
        }

        __syncthreads();

        if (c == 16) {
            // GEMM1 epilogue: BN+ReLU, hi/lo split, write hs (accs hold full GEMM1 result)
            #pragma unroll
            for (int mt = 0; mt < 2; mt++)
                #pragma unroll
                for (int nt = 0; nt < 4; nt++) {
                    int r0 = wm + mt * 16 + qr;
                    int nc = wn + nt * 8 + qc;
                    float s0 = sscale[r0],     f0 = sshift[r0];
                    float s1 = sscale[r0 + 8], f1 = sshift[r0 + 8];
                    float v00 = fmaxf(fmaf(acc[mt][nt][0], s0, f0), 0.f);
                    float v01 = fmaxf(fmaf(acc[mt][nt][1], s0, f0), 0.f);
                    float v10 = fmaxf(fmaf(acc[mt][nt][2], s1, f1), 0.f);
                    float v11 = fmaxf(fmaf(acc[mt][nt][3], s1, f1), 0.f);
                    __nv_bfloat162 hp0 = __floats2bfloat162_rn(v00, v01);
                    __nv_bfloat162 lp0 = __floats2bfloat162_rn(v00 - __bfloat162float(hp0.x),
                                                               v01 - __bfloat162float(hp0.y));
                    __nv_bfloat162 hp1 = __floats2bfloat162_rn(v10, v11);
                    __nv_bfloat162 lp1 = __floats2bfloat162_rn(v10 - __bfloat162float(hp1.x),
                                                               v11 - __bfloat162float(hp1.y));
                    uint32_t o0 = SW128((uint32_t)r0 * 128 + nc * 2);
                    uint32_t o1 = SW128((uint32_t)(r0 + 8) * 128 + nc * 2);
                    *(uint32_t*)(smem + OFF_HS_HI + o0) = *(uint32_t*)&hp0;
                    *(uint32_t*)(smem + OFF_HS_LO + o0) = *(uint32_t*)&lp0;
                    *(uint32_t*)(smem + OFF_HS_HI + o1) = *(uint32_t*)&hp1;
                    *(uint32_t*)(smem + OFF_HS_LO + o1) = *(uint32_t*)&lp1;
                }
            __syncthreads();
        }

        if (c + 1 < 32) issue_chunk(c + 1);

        const uint32_t abase = OFF_A + (uint32_t)(c & 1) * 16384;
        if (c < 16) {
            const uint32_t bbase = OFF_B + (uint32_t)(c & 1) * 8192;
            compute_chunk(sb, abase, bbase, bbase + 4096, 0, wm, wn, m_off, ko_off, acc);
        } else {
            const int j = c - 16, mc = j >> 2, kc = j & 3;
            if (kc == 0) {
                #pragma unroll
                for (int mt = 0; mt < 2; mt++)
                    #pragma unroll
                    for (int nt = 0; nt < 4; nt++)
                        #pragma unroll
                        for (int jj = 0; jj < 4; jj++) acc[mt][nt][jj] = 0.f;
            }
            compute_chunk(sb, abase, OFF_HS_HI, OFF_HS_LO, kc * 32, wm, wn, m_off, ko_off, acc);
            if (kc == 3) {
                #pragma unroll
                for (int mt = 0; mt < 2; mt++)
                    #pragma unroll
                    for (int nt = 0; nt < 4; nt++) {
                        int m = mc * HIDN + wm + mt * 16 + qr;
                        float* orow = out + ((size_t)b * CC + m) * HWN + p0 + wn + nt * 8 + qc;
                        *(float2*)orow                     = make_float2(acc[mt][nt][0], acc[mt][nt][1]);
                        *(float2*)(orow + (size_t)8 * HWN) = make_float2(acc[mt][nt][2], acc[mt][nt][3]);
                    }
            }
        }
    }
}

extern "C" void kernel_launch(void* const* d_in, const int* in_sizes, int n_in,
                              void* d_out, int out_size)
{
    const float* x      = (const float*)d_in[0];
    const int*   mod    = (const int*)  d_in[1];
    const float* w1_rgb = (const float*)d_in[2];
    const float* rm_rgb = (const float*)d_in[3];
    const float* rv_rgb = (const float*)d_in[4];
    const float* g_rgb  = (const float*)d_in[5];
    const float* b_rgb  = (const float*)d_in[6];
    const float* w2_rgb = (const float*)d_in[7];
    const float* w1_inf = (const float*)d_in[8];
    const float* rm_inf = (const float*)d_in[9];
    const float* rv_inf = (const float*)d_in[10];
    const float* g_inf  = (const float*)d_in[11];
    const float* b_inf  = (const float*)d_in[12];
    const float* w2_inf = (const float*)d_in[13];
    float* out = (float*)d_out;

    const int B = in_sizes[1];

    prep_kernel<<<1024, 256>>>(w1_rgb, w2_rgb, w1_inf, w2_inf,
                               rm_rgb, rv_rgb, g_rgb, b_rgb,
                               rm_inf, rv_inf, g_inf, b_inf);

    cudaFuncSetAttribute(msp_pipe, cudaFuncAttributeMaxDynamicSharedMemorySize, SM_TOTAL);
    dim3 grid(HWN / NT, B);
    msp_pipe<<<grid, 256, SM_TOTAL>>>(x, mod, out);
}